// round 16
// baseline (speedup 1.0000x reference)
#include <cuda_runtime.h>
#include <cuda_fp16.h>
#include <math.h>

#define NF 2048
#define M2 (NF * 135)            // conv2 GEMM rows = 276480

// ---------------- scratch (device globals: no allocations allowed) ----------
__device__ float g_pool1[NF * 64 * 8 * 14];     // 58.7 MB
__device__ float g_feats[NF * 1920];            // 15.7 MB
__device__ float g_xproj[NF * 5760];            // 47.2 MB
__device__ __half g_whh_h[5760 * 1920];         // 22.1 MB
__device__ uint4 g_msg[NF + 1][960];            // 31.5 MB
__device__ __align__(16) float g_im2col[(size_t)M2 * 1024];  // 1.13 GB
__device__ __align__(16) float g_conv2s[(size_t)M2 * 128];   // 141 MB

// un-hoistable L2 16B load / store (single-instr, un-torn)
__device__ __forceinline__ uint4 ld_cg_u4(const uint4* p) {
    uint4 v;
    asm volatile("ld.global.cg.v4.u32 {%0,%1,%2,%3}, [%4];"
                 : "=r"(v.x), "=r"(v.y), "=r"(v.z), "=r"(v.w) : "l"(p) : "memory");
    return v;
}
__device__ __forceinline__ void st_cg_u4(uint4* p, uint4 v) {
    asm volatile("st.global.cg.v4.u32 [%0], {%1,%2,%3,%4};"
                 :: "l"(p), "r"(v.x), "r"(v.y), "r"(v.z), "r"(v.w) : "memory");
}

// ---------------- conv1 (9x9, pad2) + sigmoid + pool3 ----------------------
#define C1_P 1600
#define C1_W 1296
#define C1_CB 16128
#define C1_SMEM ((C1_P + C1_W + C1_CB) * 4)

__global__ void conv1_kernel(const float* __restrict__ x,
                             const float* __restrict__ w,
                             const float* __restrict__ b) {
    extern __shared__ float sm[];
    float* P  = sm;
    float* W  = sm + C1_P;
    float* CB = sm + C1_P + C1_W;
    __shared__ float sb[16];
    const int n = blockIdx.x, c0 = blockIdx.y * 16;
    const int tid = threadIdx.x;

    for (int i = tid; i < C1_P; i += 256) P[i] = 0.f;
    for (int i = tid; i < C1_W; i += 256) W[i] = w[c0 * 81 + i];
    if (tid < 16) sb[tid] = b[c0 + tid];
    __syncthreads();
    for (int i = tid; i < 28 * 46; i += 256) {
        int r = i / 46, c = i % 46;
        P[(r + 2) * 50 + (c + 2)] = x[n * 1288 + i];
    }
    __syncthreads();

    for (int task = tid; task < 2688; task += 256) {
        int c = task / 168, rem = task % 168;
        int i = rem / 7, j0 = (rem % 7) * 6;
        float acc[6] = {0.f, 0.f, 0.f, 0.f, 0.f, 0.f};
        const float* wc = W + c * 81;
        #pragma unroll
        for (int ky = 0; ky < 9; ky++) {
            const float* pr = P + (i + ky) * 50 + j0;
            float xv[14];
            #pragma unroll
            for (int u = 0; u < 14; u++) xv[u] = pr[u];
            #pragma unroll
            for (int kx = 0; kx < 9; kx++) {
                float wv = wc[ky * 9 + kx];
                #pragma unroll
                for (int jj = 0; jj < 6; jj++)
                    acc[jj] = fmaf(xv[kx + jj], wv, acc[jj]);
            }
        }
        float bb = sb[c];
        #pragma unroll
        for (int jj = 0; jj < 6; jj++)
            CB[(c * 24 + i) * 42 + j0 + jj] = 1.f / (1.f + expf(-(acc[jj] + bb)));
    }
    __syncthreads();

    for (int task = tid; task < 1792; task += 256) {
        int c = task / 112, rem = task % 112;
        int py = rem / 14, px = rem % 14;
        float m = -3.4e38f;
        #pragma unroll
        for (int dy = 0; dy < 3; dy++)
            #pragma unroll
            for (int dx = 0; dx < 3; dx++)
                m = fmaxf(m, CB[(c * 24 + 3 * py + dy) * 42 + 3 * px + dx]);
        g_pool1[((n * 64 + c0 + c) * 8 + py) * 14 + px] = m;
    }
}

// ---------------- im2col for conv2: [276480, 1024] fp32 --------------------
// row = frame*135 + oy*15 + ox ; k = ic*16 + ky*4 + kx
__global__ void im2col_kernel() {
    const int row = blockIdx.x;
    const int frame = row / 135, pos = row % 135;
    const int oy = pos / 15, ox = pos % 15;
    const int k0 = threadIdx.x * 4;          // kx spans 0..3 (aligned)
    const int ic = k0 >> 4;
    const int ky = (k0 >> 2) & 3;
    const int iy = oy + ky - 2;
    float t0 = 0.f, t1 = 0.f, t2 = 0.f, t3 = 0.f;
    if (iy >= 0 && iy < 8) {
        const float* src = g_pool1 + ((size_t)(frame * 64 + ic) * 8 + iy) * 14;
        const int ix = ox - 2;
        if (ix >= 0 && ix + 3 < 14) {
            t0 = src[ix]; t1 = src[ix + 1]; t2 = src[ix + 2]; t3 = src[ix + 3];
        } else {
            if (ix >= 0 && ix < 14)     t0 = src[ix];
            if (ix + 1 >= 0 && ix + 1 < 14) t1 = src[ix + 1];
            if (ix + 2 >= 0 && ix + 2 < 14) t2 = src[ix + 2];
            if (ix + 3 >= 0 && ix + 3 < 14) t3 = src[ix + 3];
        }
    }
    float4 v = make_float4(t0, t1, t2, t3);
    *(float4*)(g_im2col + (size_t)row * 1024 + k0) = v;
}

// ---------------- 3xTF32 helpers ------------------------------------------
#define GP 136

__device__ __forceinline__ void tf32_split(float x, unsigned& hi, unsigned& lo) {
    unsigned h;
    asm("cvt.rna.tf32.f32 %0, %1;" : "=r"(h) : "f"(x));
    float l = x - __uint_as_float(h);
    unsigned lb;
    asm("cvt.rna.tf32.f32 %0, %1;" : "=r"(lb) : "f"(l));
    hi = h; lo = lb;
}

#define MMA_TF32(c, a, b0, b1) \
    asm volatile("mma.sync.aligned.m16n8k8.row.col.f32.tf32.tf32.f32 " \
        "{%0,%1,%2,%3}, {%4,%5,%6,%7}, {%8,%9}, {%0,%1,%2,%3};" \
        : "+f"((c)[0]), "+f"((c)[1]), "+f"((c)[2]), "+f"((c)[3]) \
        : "r"((a)[0]), "r"((a)[1]), "r"((a)[2]), "r"((a)[3]), "r"(b0), "r"(b1))

// Shared 3xTF32 GEMM body: C128x128 tile, A[row-major,lda], B[row-major,ldb(=K)]
// templated on K-steps; epilogue selected by flag (0: +bias -> g_xproj,
// 1: sigmoid(+bias) -> g_conv2s).
template <int KSTEPS, int EPI>
__device__ __forceinline__ void gemm128_tc_body(const float* Abase, int lda,
                                                const float* Bbase,
                                                const float* __restrict__ bias,
                                                int m0, int n0) {
    __shared__ unsigned sAh[2][8][GP];
    __shared__ unsigned sAl[2][8][GP];
    __shared__ unsigned sBh[2][8][GP];
    __shared__ unsigned sBl[2][8][GP];

    const int tid = threadIdx.x;
    const int warp = tid >> 5, lane = tid & 31;
    const int wm = warp & 3;
    const int wn = warp >> 2;
    const int gid = lane >> 2, tig = lane & 3;

    float c[2][8][4];
    #pragma unroll
    for (int i = 0; i < 2; i++)
        #pragma unroll
        for (int j = 0; j < 8; j++)
            #pragma unroll
            for (int q = 0; q < 4; q++) c[i][j][q] = 0.f;

    const int pm = tid >> 1;
    const int pk = (tid & 1) * 4;
    const float* Ag = Abase + (size_t)(m0 + pm) * lda + pk;
    const float* Bg = Bbase + (size_t)(n0 + pm) * lda + pk;

    {
        float4 ra = __ldg((const float4*)Ag);
        float4 rb = __ldg((const float4*)Bg);
        unsigned h, l;
        tf32_split(ra.x, h, l); sAh[0][pk+0][pm] = h; sAl[0][pk+0][pm] = l;
        tf32_split(ra.y, h, l); sAh[0][pk+1][pm] = h; sAl[0][pk+1][pm] = l;
        tf32_split(ra.z, h, l); sAh[0][pk+2][pm] = h; sAl[0][pk+2][pm] = l;
        tf32_split(ra.w, h, l); sAh[0][pk+3][pm] = h; sAl[0][pk+3][pm] = l;
        tf32_split(rb.x, h, l); sBh[0][pk+0][pm] = h; sBl[0][pk+0][pm] = l;
        tf32_split(rb.y, h, l); sBh[0][pk+1][pm] = h; sBl[0][pk+1][pm] = l;
        tf32_split(rb.z, h, l); sBh[0][pk+2][pm] = h; sBl[0][pk+2][pm] = l;
        tf32_split(rb.w, h, l); sBh[0][pk+3][pm] = h; sBl[0][pk+3][pm] = l;
    }
    __syncthreads();

    int buf = 0;
    for (int ks = 0; ks < KSTEPS; ks++) {
        float4 na, nb;
        const bool more = (ks < KSTEPS - 1);
        if (more) {
            na = __ldg((const float4*)(Ag + (ks + 1) * 8));
            nb = __ldg((const float4*)(Bg + (ks + 1) * 8));
        }

        unsigned ah[2][4], al[2][4];
        #pragma unroll
        for (int mt = 0; mt < 2; mt++) {
            int r0 = wm * 32 + mt * 16 + gid;
            ah[mt][0] = sAh[buf][tig    ][r0];
            ah[mt][1] = sAh[buf][tig    ][r0 + 8];
            ah[mt][2] = sAh[buf][tig + 4][r0];
            ah[mt][3] = sAh[buf][tig + 4][r0 + 8];
            al[mt][0] = sAl[buf][tig    ][r0];
            al[mt][1] = sAl[buf][tig    ][r0 + 8];
            al[mt][2] = sAl[buf][tig + 4][r0];
            al[mt][3] = sAl[buf][tig + 4][r0 + 8];
        }
        #pragma unroll
        for (int nt = 0; nt < 8; nt++) {
            int cb = wn * 64 + nt * 8 + gid;
            unsigned bh0 = sBh[buf][tig    ][cb];
            unsigned bh1 = sBh[buf][tig + 4][cb];
            unsigned bl0 = sBl[buf][tig    ][cb];
            unsigned bl1 = sBl[buf][tig + 4][cb];
            #pragma unroll
            for (int mt = 0; mt < 2; mt++) {
                MMA_TF32(c[mt][nt], ah[mt], bh0, bh1);
                MMA_TF32(c[mt][nt], ah[mt], bl0, bl1);
                MMA_TF32(c[mt][nt], al[mt], bh0, bh1);
            }
        }

        if (more) {
            int nx = buf ^ 1;
            unsigned h, l;
            tf32_split(na.x, h, l); sAh[nx][pk+0][pm] = h; sAl[nx][pk+0][pm] = l;
            tf32_split(na.y, h, l); sAh[nx][pk+1][pm] = h; sAl[nx][pk+1][pm] = l;
            tf32_split(na.z, h, l); sAh[nx][pk+2][pm] = h; sAl[nx][pk+2][pm] = l;
            tf32_split(na.w, h, l); sAh[nx][pk+3][pm] = h; sAl[nx][pk+3][pm] = l;
            tf32_split(nb.x, h, l); sBh[nx][pk+0][pm] = h; sBl[nx][pk+0][pm] = l;
            tf32_split(nb.y, h, l); sBh[nx][pk+1][pm] = h; sBl[nx][pk+1][pm] = l;
            tf32_split(nb.z, h, l); sBh[nx][pk+2][pm] = h; sBl[nx][pk+2][pm] = l;
            tf32_split(nb.w, h, l); sBh[nx][pk+3][pm] = h; sBl[nx][pk+3][pm] = l;
        }
        __syncthreads();
        buf ^= 1;
    }

    #pragma unroll
    for (int mt = 0; mt < 2; mt++) {
        int r0 = m0 + wm * 32 + mt * 16 + gid;
        #pragma unroll
        for (int nt = 0; nt < 8; nt++) {
            int col = n0 + wn * 64 + nt * 8 + 2 * tig;
            float b0 = __ldg(bias + col), b1 = __ldg(bias + col + 1);
            if (EPI == 0) {
                float2 v0 = make_float2(c[mt][nt][0] + b0, c[mt][nt][1] + b1);
                float2 v1 = make_float2(c[mt][nt][2] + b0, c[mt][nt][3] + b1);
                *(float2*)(g_xproj + (size_t)r0 * 5760 + col) = v0;
                *(float2*)(g_xproj + (size_t)(r0 + 8) * 5760 + col) = v1;
            } else {
                float2 v0 = make_float2(
                    1.f / (1.f + expf(-(c[mt][nt][0] + b0))),
                    1.f / (1.f + expf(-(c[mt][nt][1] + b1))));
                float2 v1 = make_float2(
                    1.f / (1.f + expf(-(c[mt][nt][2] + b0))),
                    1.f / (1.f + expf(-(c[mt][nt][3] + b1))));
                *(float2*)(g_conv2s + (size_t)r0 * 128 + col) = v0;
                *(float2*)(g_conv2s + (size_t)(r0 + 8) * 128 + col) = v1;
            }
        }
    }
}

// conv2 GEMM: [276480,1024] x [128,1024]^T, sigmoid epilogue -> g_conv2s
__global__ void __launch_bounds__(256) conv2_gemm_tc(const float* __restrict__ W2,
                                                     const float* __restrict__ b2) {
    gemm128_tc_body<128, 1>(g_im2col, 1024, W2, b2, blockIdx.x * 128, 0);
}

// x_proj GEMM: [2048,1920] x [5760,1920]^T + b_ih -> g_xproj
__global__ void __launch_bounds__(256) gemm_xproj_tc(const float* __restrict__ W,
                                                     const float* __restrict__ bias) {
    gemm128_tc_body<240, 0>(g_feats, 1920, W, bias, blockIdx.x * 128, blockIdx.y * 128);
}

// ---------------- pool2: 3x3 stride-3 max over g_conv2s -> g_feats ---------
__global__ void pool2_kernel() {
    const int frame = blockIdx.x;
    for (int task = threadIdx.x; task < 1920; task += 256) {
        int oc = task / 15, rem = task % 15;
        int py = rem / 5, px = rem % 5;
        float m = -3.4e38f;
        #pragma unroll
        for (int dy = 0; dy < 3; dy++)
            #pragma unroll
            for (int dx = 0; dx < 3; dx++)
                m = fmaxf(m, g_conv2s[((size_t)frame * 135 +
                        (3 * py + dy) * 15 + (3 * px + dx)) * 128 + oc]);
        g_feats[frame * 1920 + oc * 15 + py * 5 + px] = m;
    }
}

// ---------------- convert w_hh fp32 -> fp16, regrouped [unit][gate][k] -----
__global__ void convert_whh(const float* __restrict__ Whh) {
    const int row = blockIdx.x;
    const int gate = row / 1920, unit = row % 1920;
    const float* src = Whh + (size_t)row * 1920;
    __half* dst = g_whh_h + ((size_t)unit * 3 + gate) * 1920;
    for (int k = threadIdx.x; k < 1920; k += 256)
        dst[k] = __float2half(src[k]);
}

// ---------------- init: zero tags, publish h0 (tag=1) ----------------------
__global__ void init_kernel(const float* __restrict__ h0) {
    const int total = (NF + 1) * 960;
    uint4* base = &g_msg[0][0];
    for (int i = blockIdx.x * blockDim.x + threadIdx.x; i < total;
         i += gridDim.x * blockDim.x) {
        uint4 v;
        if (i < 960) {
            v.x = 1u; v.y = 0u;
            v.z = __float_as_uint(h0[2 * i]);
            v.w = __float_as_uint(h0[2 * i + 1]);
        } else {
            v.x = 0u; v.y = 0u; v.z = 0u; v.w = 0u;
        }
        st_cg_u4(base + i, v);
    }
}

// ---------------- persistent GRU scan: packed-message dataflow (R6) --------
#define W_HALVES (16 * 3 * 1920)
#define GRU_SMEM (W_HALVES * 2 + 1920 * 4)

__global__ void __launch_bounds__(512) gru_kernel(const float* __restrict__ bhh) {
    extern __shared__ __align__(16) char smraw[];
    __half* sw = (__half*)smraw;
    float* sh = (float*)(smraw + W_HALVES * 2);
    __shared__ float s_new[16];
    const int tid = threadIdx.x;
    const int cta = blockIdx.x;

    {
        const uint4* src = (const uint4*)(g_whh_h + (size_t)cta * W_HALVES);
        uint4* dst = (uint4*)sw;
        for (int i = tid; i < W_HALVES / 8; i += 512) dst[i] = src[i];
    }
    const int ul = tid >> 5, lane = tid & 31;
    const int wi = cta * 16 + ul;
    const __half2* wr2 = (const __half2*)(sw + ul * 3 * 1920);
    const __half2* wz2 = wr2 + 960;
    const __half2* wn2 = wz2 + 960;
    const float br = bhh[wi], bz = bhh[1920 + wi], bn = bhh[3840 + wi];
    const bool has2 = (tid < 448);
    __syncthreads();

    for (int t = 0; t < 2048; t++) {
        const unsigned want = (unsigned)(t + 1);
        {
            uint4 v0, v1;
            bool d0 = false, d1 = !has2;
            do {
                if (!d0) { v0 = ld_cg_u4(&g_msg[t][tid]);       d0 = (v0.x == want); }
                if (!d1) { v1 = ld_cg_u4(&g_msg[t][tid + 512]); d1 = (v1.x == want); }
                if (!(d0 && d1)) __nanosleep(30);
            } while (!(d0 && d1));
            sh[2 * tid]     = __uint_as_float(v0.z);
            sh[2 * tid + 1] = __uint_as_float(v0.w);
            if (has2) {
                sh[2 * (tid + 512)]     = __uint_as_float(v1.z);
                sh[2 * (tid + 512) + 1] = __uint_as_float(v1.w);
            }
        }

        float xr = 0.f, xz = 0.f, xn = 0.f;
        if (lane == 0) {
            const float* xp = g_xproj + (size_t)t * 5760;
            xr = __ldg(xp + wi); xz = __ldg(xp + 1920 + wi); xn = __ldg(xp + 3840 + wi);
        }
        __syncthreads();
        const float2* sh2 = (const float2*)sh;

        float sr = 0.f, sz = 0.f, sn = 0.f;
        #pragma unroll 6
        for (int it = 0; it < 30; it++) {
            const int idx = it * 32 + lane;
            float2 h2 = sh2[idx];
            float2 a = __half22float2(wr2[idx]);
            float2 b = __half22float2(wz2[idx]);
            float2 c = __half22float2(wn2[idx]);
            sr = fmaf(h2.y, a.y, fmaf(h2.x, a.x, sr));
            sz = fmaf(h2.y, b.y, fmaf(h2.x, b.x, sz));
            sn = fmaf(h2.y, c.y, fmaf(h2.x, c.x, sn));
        }
        #pragma unroll
        for (int off = 16; off > 0; off >>= 1) {
            sr += __shfl_xor_sync(0xffffffffu, sr, off);
            sz += __shfl_xor_sync(0xffffffffu, sz, off);
            sn += __shfl_xor_sync(0xffffffffu, sn, off);
        }
        if (lane == 0) {
            float r  = 1.f / (1.f + expf(-(xr + sr + br)));
            float z  = 1.f / (1.f + expf(-(xz + sz + bz)));
            float nn = tanhf(xn + r * (sn + bn));
            s_new[ul] = (1.f - z) * nn + z * sh[wi];
        }
        __syncthreads();
        if (tid < 8) {
            uint4 v;
            v.x = want + 1u; v.y = 0u;
            v.z = __float_as_uint(s_new[2 * tid]);
            v.w = __float_as_uint(s_new[2 * tid + 1]);
            st_cg_u4(&g_msg[t + 1][cta * 8 + tid], v);
        }
    }
}

// ---------------- final FC: [1,1920] x [2,1920]^T + fc_b -------------------
__global__ void fc_kernel(const float* __restrict__ fcw,
                          const float* __restrict__ fcb,
                          float* __restrict__ out) {
    __shared__ float red0[256], red1[256];
    const int tid = threadIdx.x;
    float s0 = 0.f, s1 = 0.f;
    for (int p = tid; p < 960; p += 256) {
        uint4 v = g_msg[NF][p];
        float h0v = __uint_as_float(v.z);
        float h1v = __uint_as_float(v.w);
        int k = 2 * p;
        s0 = fmaf(h0v, fcw[k], s0);     s0 = fmaf(h1v, fcw[k + 1], s0);
        s1 = fmaf(h0v, fcw[1920 + k], s1); s1 = fmaf(h1v, fcw[1920 + k + 1], s1);
    }
    red0[tid] = s0; red1[tid] = s1;
    __syncthreads();
    for (int s = 128; s > 0; s >>= 1) {
        if (tid < s) { red0[tid] += red0[tid + s]; red1[tid] += red1[tid + s]; }
        __syncthreads();
    }
    if (tid == 0) { out[0] = red0[0] + fcb[0]; out[1] = red1[0] + fcb[1]; }
}

// ---------------- launcher --------------------------------------------------
extern "C" void kernel_launch(void* const* d_in, const int* in_sizes, int n_in,
                              void* d_out, int out_size) {
    const float* x    = (const float*)d_in[0];
    const float* c1w  = (const float*)d_in[1];
    const float* c1b  = (const float*)d_in[2];
    const float* c2w  = (const float*)d_in[3];
    const float* c2b  = (const float*)d_in[4];
    const float* wih  = (const float*)d_in[5];
    const float* whh  = (const float*)d_in[6];
    const float* bih  = (const float*)d_in[7];
    const float* bhh  = (const float*)d_in[8];
    const float* fcw  = (const float*)d_in[9];
    const float* fcb  = (const float*)d_in[10];
    const float* h0   = (const float*)d_in[11];
    (void)in_sizes; (void)n_in; (void)out_size;

    cudaFuncSetAttribute(conv1_kernel, cudaFuncAttributeMaxDynamicSharedMemorySize, C1_SMEM);
    cudaFuncSetAttribute(gru_kernel, cudaFuncAttributeMaxDynamicSharedMemorySize, GRU_SMEM);

    conv1_kernel<<<dim3(NF, 4), 256, C1_SMEM>>>(x, c1w, c1b);
    im2col_kernel<<<M2, 256>>>();
    conv2_gemm_tc<<<M2 / 128, 256>>>(c2w, c2b);
    pool2_kernel<<<NF, 256>>>();
    gemm_xproj_tc<<<dim3(16, 45), 256>>>(wih, bih);
    convert_whh<<<5760, 256>>>(whh);
    init_kernel<<<512, 256>>>(h0);
    gru_kernel<<<120, 512, GRU_SMEM>>>(bhh);
    fc_kernel<<<1, 256>>>(fcw, fcb, (float*)d_out);
}

// round 17
// speedup vs baseline: 1.0018x; 1.0018x over previous
#include <cuda_runtime.h>
#include <cuda_fp16.h>
#include <math.h>

#define NF 2048
#define M2 (NF * 135)            // conv2 GEMM rows = 276480

// ---------------- scratch (device globals: no allocations allowed) ----------
__device__ float g_pool1[NF * 64 * 8 * 14];     // 58.7 MB
__device__ float g_feats[NF * 1920];            // 15.7 MB
__device__ float g_xproj[NF * 5760];            // 47.2 MB
__device__ __half g_whh_h[5760 * 1920];         // 22.1 MB
__device__ uint4 g_msg[NF + 1][960];            // 31.5 MB
__device__ __align__(16) float g_im2col[(size_t)M2 * 1024];  // 1.13 GB
__device__ __align__(16) float g_conv2s[(size_t)M2 * 128];   // 141 MB

// un-hoistable L2 16B load / store (single-instr, un-torn)
__device__ __forceinline__ uint4 ld_cg_u4(const uint4* p) {
    uint4 v;
    asm volatile("ld.global.cg.v4.u32 {%0,%1,%2,%3}, [%4];"
                 : "=r"(v.x), "=r"(v.y), "=r"(v.z), "=r"(v.w) : "l"(p) : "memory");
    return v;
}
__device__ __forceinline__ void st_cg_u4(uint4* p, uint4 v) {
    asm volatile("st.global.cg.v4.u32 [%0], {%1,%2,%3,%4};"
                 :: "l"(p), "r"(v.x), "r"(v.y), "r"(v.z), "r"(v.w) : "memory");
}

// ---------------- conv1 (9x9, pad2) + sigmoid + pool3 ----------------------
#define C1_P 1600
#define C1_W 1296
#define C1_CB 16128
#define C1_SMEM ((C1_P + C1_W + C1_CB) * 4)

__global__ void conv1_kernel(const float* __restrict__ x,
                             const float* __restrict__ w,
                             const float* __restrict__ b) {
    extern __shared__ float sm[];
    float* P  = sm;
    float* W  = sm + C1_P;
    float* CB = sm + C1_P + C1_W;
    __shared__ float sb[16];
    const int n = blockIdx.x, c0 = blockIdx.y * 16;
    const int tid = threadIdx.x;

    for (int i = tid; i < C1_P; i += 256) P[i] = 0.f;
    for (int i = tid; i < C1_W; i += 256) W[i] = w[c0 * 81 + i];
    if (tid < 16) sb[tid] = b[c0 + tid];
    __syncthreads();
    for (int i = tid; i < 28 * 46; i += 256) {
        int r = i / 46, c = i % 46;
        P[(r + 2) * 50 + (c + 2)] = x[n * 1288 + i];
    }
    __syncthreads();

    for (int task = tid; task < 2688; task += 256) {
        int c = task / 168, rem = task % 168;
        int i = rem / 7, j0 = (rem % 7) * 6;
        float acc[6] = {0.f, 0.f, 0.f, 0.f, 0.f, 0.f};
        const float* wc = W + c * 81;
        #pragma unroll
        for (int ky = 0; ky < 9; ky++) {
            const float* pr = P + (i + ky) * 50 + j0;
            float xv[14];
            #pragma unroll
            for (int u = 0; u < 14; u++) xv[u] = pr[u];
            #pragma unroll
            for (int kx = 0; kx < 9; kx++) {
                float wv = wc[ky * 9 + kx];
                #pragma unroll
                for (int jj = 0; jj < 6; jj++)
                    acc[jj] = fmaf(xv[kx + jj], wv, acc[jj]);
            }
        }
        float bb = sb[c];
        #pragma unroll
        for (int jj = 0; jj < 6; jj++)
            CB[(c * 24 + i) * 42 + j0 + jj] = 1.f / (1.f + expf(-(acc[jj] + bb)));
    }
    __syncthreads();

    for (int task = tid; task < 1792; task += 256) {
        int c = task / 112, rem = task % 112;
        int py = rem / 14, px = rem % 14;
        float m = -3.4e38f;
        #pragma unroll
        for (int dy = 0; dy < 3; dy++)
            #pragma unroll
            for (int dx = 0; dx < 3; dx++)
                m = fmaxf(m, CB[(c * 24 + 3 * py + dy) * 42 + 3 * px + dx]);
        g_pool1[((n * 64 + c0 + c) * 8 + py) * 14 + px] = m;
    }
}

// ---------------- im2col for conv2: [276480, 1024] fp32 --------------------
// row = frame*135 + oy*15 + ox ; k = ic*16 + ky*4 + kx
__global__ void im2col_kernel() {
    const int row = blockIdx.x;
    const int frame = row / 135, pos = row % 135;
    const int oy = pos / 15, ox = pos % 15;
    const int k0 = threadIdx.x * 4;          // kx spans 0..3 (aligned)
    const int ic = k0 >> 4;
    const int ky = (k0 >> 2) & 3;
    const int iy = oy + ky - 2;
    float t0 = 0.f, t1 = 0.f, t2 = 0.f, t3 = 0.f;
    if (iy >= 0 && iy < 8) {
        const float* src = g_pool1 + ((size_t)(frame * 64 + ic) * 8 + iy) * 14;
        const int ix = ox - 2;
        if (ix >= 0 && ix + 3 < 14) {
            t0 = src[ix]; t1 = src[ix + 1]; t2 = src[ix + 2]; t3 = src[ix + 3];
        } else {
            if (ix >= 0 && ix < 14)     t0 = src[ix];
            if (ix + 1 >= 0 && ix + 1 < 14) t1 = src[ix + 1];
            if (ix + 2 >= 0 && ix + 2 < 14) t2 = src[ix + 2];
            if (ix + 3 >= 0 && ix + 3 < 14) t3 = src[ix + 3];
        }
    }
    float4 v = make_float4(t0, t1, t2, t3);
    *(float4*)(g_im2col + (size_t)row * 1024 + k0) = v;
}

// ---------------- 3xTF32 helpers ------------------------------------------
#define GP 136

__device__ __forceinline__ void tf32_split(float x, unsigned& hi, unsigned& lo) {
    unsigned h;
    asm("cvt.rna.tf32.f32 %0, %1;" : "=r"(h) : "f"(x));
    float l = x - __uint_as_float(h);
    unsigned lb;
    asm("cvt.rna.tf32.f32 %0, %1;" : "=r"(lb) : "f"(l));
    hi = h; lo = lb;
}

#define MMA_TF32(c, a, b0, b1) \
    asm volatile("mma.sync.aligned.m16n8k8.row.col.f32.tf32.tf32.f32 " \
        "{%0,%1,%2,%3}, {%4,%5,%6,%7}, {%8,%9}, {%0,%1,%2,%3};" \
        : "+f"((c)[0]), "+f"((c)[1]), "+f"((c)[2]), "+f"((c)[3]) \
        : "r"((a)[0]), "r"((a)[1]), "r"((a)[2]), "r"((a)[3]), "r"(b0), "r"(b1))

// Shared 3xTF32 GEMM body: C128x128 tile, A[row-major,lda], B[row-major,ldb(=K)]
// templated on K-steps; epilogue selected by flag (0: +bias -> g_xproj,
// 1: sigmoid(+bias) -> g_conv2s).
template <int KSTEPS, int EPI>
__device__ __forceinline__ void gemm128_tc_body(const float* Abase, int lda,
                                                const float* Bbase,
                                                const float* __restrict__ bias,
                                                int m0, int n0) {
    __shared__ unsigned sAh[2][8][GP];
    __shared__ unsigned sAl[2][8][GP];
    __shared__ unsigned sBh[2][8][GP];
    __shared__ unsigned sBl[2][8][GP];

    const int tid = threadIdx.x;
    const int warp = tid >> 5, lane = tid & 31;
    const int wm = warp & 3;
    const int wn = warp >> 2;
    const int gid = lane >> 2, tig = lane & 3;

    float c[2][8][4];
    #pragma unroll
    for (int i = 0; i < 2; i++)
        #pragma unroll
        for (int j = 0; j < 8; j++)
            #pragma unroll
            for (int q = 0; q < 4; q++) c[i][j][q] = 0.f;

    const int pm = tid >> 1;
    const int pk = (tid & 1) * 4;
    const float* Ag = Abase + (size_t)(m0 + pm) * lda + pk;
    const float* Bg = Bbase + (size_t)(n0 + pm) * lda + pk;

    {
        float4 ra = __ldg((const float4*)Ag);
        float4 rb = __ldg((const float4*)Bg);
        unsigned h, l;
        tf32_split(ra.x, h, l); sAh[0][pk+0][pm] = h; sAl[0][pk+0][pm] = l;
        tf32_split(ra.y, h, l); sAh[0][pk+1][pm] = h; sAl[0][pk+1][pm] = l;
        tf32_split(ra.z, h, l); sAh[0][pk+2][pm] = h; sAl[0][pk+2][pm] = l;
        tf32_split(ra.w, h, l); sAh[0][pk+3][pm] = h; sAl[0][pk+3][pm] = l;
        tf32_split(rb.x, h, l); sBh[0][pk+0][pm] = h; sBl[0][pk+0][pm] = l;
        tf32_split(rb.y, h, l); sBh[0][pk+1][pm] = h; sBl[0][pk+1][pm] = l;
        tf32_split(rb.z, h, l); sBh[0][pk+2][pm] = h; sBl[0][pk+2][pm] = l;
        tf32_split(rb.w, h, l); sBh[0][pk+3][pm] = h; sBl[0][pk+3][pm] = l;
    }
    __syncthreads();

    int buf = 0;
    for (int ks = 0; ks < KSTEPS; ks++) {
        float4 na, nb;
        const bool more = (ks < KSTEPS - 1);
        if (more) {
            na = __ldg((const float4*)(Ag + (ks + 1) * 8));
            nb = __ldg((const float4*)(Bg + (ks + 1) * 8));
        }

        unsigned ah[2][4], al[2][4];
        #pragma unroll
        for (int mt = 0; mt < 2; mt++) {
            int r0 = wm * 32 + mt * 16 + gid;
            ah[mt][0] = sAh[buf][tig    ][r0];
            ah[mt][1] = sAh[buf][tig    ][r0 + 8];
            ah[mt][2] = sAh[buf][tig + 4][r0];
            ah[mt][3] = sAh[buf][tig + 4][r0 + 8];
            al[mt][0] = sAl[buf][tig    ][r0];
            al[mt][1] = sAl[buf][tig    ][r0 + 8];
            al[mt][2] = sAl[buf][tig + 4][r0];
            al[mt][3] = sAl[buf][tig + 4][r0 + 8];
        }
        #pragma unroll
        for (int nt = 0; nt < 8; nt++) {
            int cb = wn * 64 + nt * 8 + gid;
            unsigned bh0 = sBh[buf][tig    ][cb];
            unsigned bh1 = sBh[buf][tig + 4][cb];
            unsigned bl0 = sBl[buf][tig    ][cb];
            unsigned bl1 = sBl[buf][tig + 4][cb];
            #pragma unroll
            for (int mt = 0; mt < 2; mt++) {
                MMA_TF32(c[mt][nt], ah[mt], bh0, bh1);
                MMA_TF32(c[mt][nt], ah[mt], bl0, bl1);
                MMA_TF32(c[mt][nt], al[mt], bh0, bh1);
            }
        }

        if (more) {
            int nx = buf ^ 1;
            unsigned h, l;
            tf32_split(na.x, h, l); sAh[nx][pk+0][pm] = h; sAl[nx][pk+0][pm] = l;
            tf32_split(na.y, h, l); sAh[nx][pk+1][pm] = h; sAl[nx][pk+1][pm] = l;
            tf32_split(na.z, h, l); sAh[nx][pk+2][pm] = h; sAl[nx][pk+2][pm] = l;
            tf32_split(na.w, h, l); sAh[nx][pk+3][pm] = h; sAl[nx][pk+3][pm] = l;
            tf32_split(nb.x, h, l); sBh[nx][pk+0][pm] = h; sBl[nx][pk+0][pm] = l;
            tf32_split(nb.y, h, l); sBh[nx][pk+1][pm] = h; sBl[nx][pk+1][pm] = l;
            tf32_split(nb.z, h, l); sBh[nx][pk+2][pm] = h; sBl[nx][pk+2][pm] = l;
            tf32_split(nb.w, h, l); sBh[nx][pk+3][pm] = h; sBl[nx][pk+3][pm] = l;
        }
        __syncthreads();
        buf ^= 1;
    }

    #pragma unroll
    for (int mt = 0; mt < 2; mt++) {
        int r0 = m0 + wm * 32 + mt * 16 + gid;
        #pragma unroll
        for (int nt = 0; nt < 8; nt++) {
            int col = n0 + wn * 64 + nt * 8 + 2 * tig;
            float b0 = __ldg(bias + col), b1 = __ldg(bias + col + 1);
            if (EPI == 0) {
                float2 v0 = make_float2(c[mt][nt][0] + b0, c[mt][nt][1] + b1);
                float2 v1 = make_float2(c[mt][nt][2] + b0, c[mt][nt][3] + b1);
                *(float2*)(g_xproj + (size_t)r0 * 5760 + col) = v0;
                *(float2*)(g_xproj + (size_t)(r0 + 8) * 5760 + col) = v1;
            } else {
                float2 v0 = make_float2(
                    1.f / (1.f + expf(-(c[mt][nt][0] + b0))),
                    1.f / (1.f + expf(-(c[mt][nt][1] + b1))));
                float2 v1 = make_float2(
                    1.f / (1.f + expf(-(c[mt][nt][2] + b0))),
                    1.f / (1.f + expf(-(c[mt][nt][3] + b1))));
                *(float2*)(g_conv2s + (size_t)r0 * 128 + col) = v0;
                *(float2*)(g_conv2s + (size_t)(r0 + 8) * 128 + col) = v1;
            }
        }
    }
}

// conv2 GEMM: [276480,1024] x [128,1024]^T, sigmoid epilogue -> g_conv2s
__global__ void __launch_bounds__(256) conv2_gemm_tc(const float* __restrict__ W2,
                                                     const float* __restrict__ b2) {
    gemm128_tc_body<128, 1>(g_im2col, 1024, W2, b2, blockIdx.x * 128, 0);
}

// x_proj GEMM: [2048,1920] x [5760,1920]^T + b_ih -> g_xproj
__global__ void __launch_bounds__(256) gemm_xproj_tc(const float* __restrict__ W,
                                                     const float* __restrict__ bias) {
    gemm128_tc_body<240, 0>(g_feats, 1920, W, bias, blockIdx.x * 128, blockIdx.y * 128);
}

// ---------------- pool2: 3x3 stride-3 max over g_conv2s -> g_feats ---------
__global__ void pool2_kernel() {
    const int frame = blockIdx.x;
    for (int task = threadIdx.x; task < 1920; task += 256) {
        int oc = task / 15, rem = task % 15;
        int py = rem / 5, px = rem % 5;
        float m = -3.4e38f;
        #pragma unroll
        for (int dy = 0; dy < 3; dy++)
            #pragma unroll
            for (int dx = 0; dx < 3; dx++)
                m = fmaxf(m, g_conv2s[((size_t)frame * 135 +
                        (3 * py + dy) * 15 + (3 * px + dx)) * 128 + oc]);
        g_feats[frame * 1920 + oc * 15 + py * 5 + px] = m;
    }
}

// ---------------- convert w_hh fp32 -> fp16, regrouped [unit][gate][k] -----
__global__ void convert_whh(const float* __restrict__ Whh) {
    const int row = blockIdx.x;
    const int gate = row / 1920, unit = row % 1920;
    const float* src = Whh + (size_t)row * 1920;
    __half* dst = g_whh_h + ((size_t)unit * 3 + gate) * 1920;
    for (int k = threadIdx.x; k < 1920; k += 256)
        dst[k] = __float2half(src[k]);
}

// ---------------- init: zero tags, publish h0 (tag=1) ----------------------
__global__ void init_kernel(const float* __restrict__ h0) {
    const int total = (NF + 1) * 960;
    uint4* base = &g_msg[0][0];
    for (int i = blockIdx.x * blockDim.x + threadIdx.x; i < total;
         i += gridDim.x * blockDim.x) {
        uint4 v;
        if (i < 960) {
            v.x = 1u; v.y = 0u;
            v.z = __float_as_uint(h0[2 * i]);
            v.w = __float_as_uint(h0[2 * i + 1]);
        } else {
            v.x = 0u; v.y = 0u; v.z = 0u; v.w = 0u;
        }
        st_cg_u4(base + i, v);
    }
}

// ---------------- persistent GRU scan: packed-message dataflow (R6) --------
#define W_HALVES (16 * 3 * 1920)
#define GRU_SMEM (W_HALVES * 2 + 1920 * 4)

__global__ void __launch_bounds__(512) gru_kernel(const float* __restrict__ bhh) {
    extern __shared__ __align__(16) char smraw[];
    __half* sw = (__half*)smraw;
    float* sh = (float*)(smraw + W_HALVES * 2);
    __shared__ float s_new[16];
    const int tid = threadIdx.x;
    const int cta = blockIdx.x;

    {
        const uint4* src = (const uint4*)(g_whh_h + (size_t)cta * W_HALVES);
        uint4* dst = (uint4*)sw;
        for (int i = tid; i < W_HALVES / 8; i += 512) dst[i] = src[i];
    }
    const int ul = tid >> 5, lane = tid & 31;
    const int wi = cta * 16 + ul;
    const __half2* wr2 = (const __half2*)(sw + ul * 3 * 1920);
    const __half2* wz2 = wr2 + 960;
    const __half2* wn2 = wz2 + 960;
    const float br = bhh[wi], bz = bhh[1920 + wi], bn = bhh[3840 + wi];
    const bool has2 = (tid < 448);
    __syncthreads();

    for (int t = 0; t < 2048; t++) {
        const unsigned want = (unsigned)(t + 1);
        {
            uint4 v0, v1;
            bool d0 = false, d1 = !has2;
            do {
                if (!d0) { v0 = ld_cg_u4(&g_msg[t][tid]);       d0 = (v0.x == want); }
                if (!d1) { v1 = ld_cg_u4(&g_msg[t][tid + 512]); d1 = (v1.x == want); }
                if (!(d0 && d1)) __nanosleep(30);
            } while (!(d0 && d1));
            sh[2 * tid]     = __uint_as_float(v0.z);
            sh[2 * tid + 1] = __uint_as_float(v0.w);
            if (has2) {
                sh[2 * (tid + 512)]     = __uint_as_float(v1.z);
                sh[2 * (tid + 512) + 1] = __uint_as_float(v1.w);
            }
        }

        float xr = 0.f, xz = 0.f, xn = 0.f;
        if (lane == 0) {
            const float* xp = g_xproj + (size_t)t * 5760;
            xr = __ldg(xp + wi); xz = __ldg(xp + 1920 + wi); xn = __ldg(xp + 3840 + wi);
        }
        __syncthreads();
        const float2* sh2 = (const float2*)sh;

        float sr = 0.f, sz = 0.f, sn = 0.f;
        #pragma unroll 6
        for (int it = 0; it < 30; it++) {
            const int idx = it * 32 + lane;
            float2 h2 = sh2[idx];
            float2 a = __half22float2(wr2[idx]);
            float2 b = __half22float2(wz2[idx]);
            float2 c = __half22float2(wn2[idx]);
            sr = fmaf(h2.y, a.y, fmaf(h2.x, a.x, sr));
            sz = fmaf(h2.y, b.y, fmaf(h2.x, b.x, sz));
            sn = fmaf(h2.y, c.y, fmaf(h2.x, c.x, sn));
        }
        #pragma unroll
        for (int off = 16; off > 0; off >>= 1) {
            sr += __shfl_xor_sync(0xffffffffu, sr, off);
            sz += __shfl_xor_sync(0xffffffffu, sz, off);
            sn += __shfl_xor_sync(0xffffffffu, sn, off);
        }
        if (lane == 0) {
            float r  = 1.f / (1.f + expf(-(xr + sr + br)));
            float z  = 1.f / (1.f + expf(-(xz + sz + bz)));
            float nn = tanhf(xn + r * (sn + bn));
            s_new[ul] = (1.f - z) * nn + z * sh[wi];
        }
        __syncthreads();
        if (tid < 8) {
            uint4 v;
            v.x = want + 1u; v.y = 0u;
            v.z = __float_as_uint(s_new[2 * tid]);
            v.w = __float_as_uint(s_new[2 * tid + 1]);
            st_cg_u4(&g_msg[t + 1][cta * 8 + tid], v);
        }
    }
}

// ---------------- final FC: [1,1920] x [2,1920]^T + fc_b -------------------
__global__ void fc_kernel(const float* __restrict__ fcw,
                          const float* __restrict__ fcb,
                          float* __restrict__ out) {
    __shared__ float red0[256], red1[256];
    const int tid = threadIdx.x;
    float s0 = 0.f, s1 = 0.f;
    for (int p = tid; p < 960; p += 256) {
        uint4 v = g_msg[NF][p];
        float h0v = __uint_as_float(v.z);
        float h1v = __uint_as_float(v.w);
        int k = 2 * p;
        s0 = fmaf(h0v, fcw[k], s0);     s0 = fmaf(h1v, fcw[k + 1], s0);
        s1 = fmaf(h0v, fcw[1920 + k], s1); s1 = fmaf(h1v, fcw[1920 + k + 1], s1);
    }
    red0[tid] = s0; red1[tid] = s1;
    __syncthreads();
    for (int s = 128; s > 0; s >>= 1) {
        if (tid < s) { red0[tid] += red0[tid + s]; red1[tid] += red1[tid + s]; }
        __syncthreads();
    }
    if (tid == 0) { out[0] = red0[0] + fcb[0]; out[1] = red1[0] + fcb[1]; }
}

// ---------------- launcher --------------------------------------------------
extern "C" void kernel_launch(void* const* d_in, const int* in_sizes, int n_in,
                              void* d_out, int out_size) {
    const float* x    = (const float*)d_in[0];
    const float* c1w  = (const float*)d_in[1];
    const float* c1b  = (const float*)d_in[2];
    const float* c2w  = (const float*)d_in[3];
    const float* c2b  = (const float*)d_in[4];
    const float* wih  = (const float*)d_in[5];
    const float* whh  = (const float*)d_in[6];
    const float* bih  = (const float*)d_in[7];
    const float* bhh  = (const float*)d_in[8];
    const float* fcw  = (const float*)d_in[9];
    const float* fcb  = (const float*)d_in[10];
    const float* h0   = (const float*)d_in[11];
    (void)in_sizes; (void)n_in; (void)out_size;

    cudaFuncSetAttribute(conv1_kernel, cudaFuncAttributeMaxDynamicSharedMemorySize, C1_SMEM);
    cudaFuncSetAttribute(gru_kernel, cudaFuncAttributeMaxDynamicSharedMemorySize, GRU_SMEM);

    conv1_kernel<<<dim3(NF, 4), 256, C1_SMEM>>>(x, c1w, c1b);
    im2col_kernel<<<M2, 256>>>();
    conv2_gemm_tc<<<M2 / 128, 256>>>(c2w, c2b);
    pool2_kernel<<<NF, 256>>>();
    gemm_xproj_tc<<<dim3(16, 45), 256>>>(wih, bih);
    convert_whh<<<5760, 256>>>(whh);
    init_kernel<<<512, 256>>>(h0);
    gru_kernel<<<120, 512, GRU_SMEM>>>(bhh);
    fc_kernel<<<1, 256>>>(fcw, fcb, (float*)d_out);
}